// round 1
// baseline (speedup 1.0000x reference)
#include <cuda_runtime.h>
#include <math.h>
#include <stdint.h>

// Problem constants
#define BATCH 2
#define SEQ   2048
#define DIM   2048
#define NHEAD 32
#define DHEAD 64
#define FFN   8192
#define LDWIN 18560              // W_in row stride (full)
#define HCOLS 10368              // used columns of W_in: q(2048)|k(64)|v(64)|ffn(8192)
#define OUTK  10240              // concat dim: attn(2048)+ffn(8192)
#define MTOK  (BATCH*SEQ)        // 4096 tokens
#define LN_EPS 1e-5f
#define QSCALE 0.125f            // 64^-0.5

// Scratch (device globals; no runtime allocation allowed)
__device__ float g_xn[(size_t)MTOK * DIM];      // layernorm output (also residual)
__device__ float g_h[(size_t)MTOK * HCOLS];     // xn @ W_in[:, :10368]
__device__ float g_attn[(size_t)MTOK * DIM];    // attention output (all heads)

// ---------------------------------------------------------------------------
// Kernel 1: LayerNorm. One block per token row, 256 threads, 2048 cols.
// ---------------------------------------------------------------------------
__global__ void ln_kernel(const float* __restrict__ x,
                          const float* __restrict__ gamma,
                          const float* __restrict__ beta,
                          float* __restrict__ xn) {
    int row = blockIdx.x;
    int tid = threadIdx.x;
    const float4* xr = reinterpret_cast<const float4*>(x + (size_t)row * DIM);
    float4 a = xr[tid];
    float4 b = xr[tid + 256];
    float s  = a.x + a.y + a.z + a.w + b.x + b.y + b.z + b.w;
    float s2 = a.x*a.x + a.y*a.y + a.z*a.z + a.w*a.w
             + b.x*b.x + b.y*b.y + b.z*b.z + b.w*b.w;
    // warp reduce
    #pragma unroll
    for (int off = 16; off > 0; off >>= 1) {
        s  += __shfl_xor_sync(0xffffffffu, s,  off);
        s2 += __shfl_xor_sync(0xffffffffu, s2, off);
    }
    __shared__ float ss[8], ss2[8];
    int wid = tid >> 5, lane = tid & 31;
    if (lane == 0) { ss[wid] = s; ss2[wid] = s2; }
    __syncthreads();
    s  = ss[0] + ss[1] + ss[2] + ss[3] + ss[4] + ss[5] + ss[6] + ss[7];
    s2 = ss2[0]+ ss2[1]+ ss2[2]+ ss2[3]+ ss2[4]+ ss2[5]+ ss2[6]+ ss2[7];
    float mean = s * (1.0f / DIM);
    float var  = s2 * (1.0f / DIM) - mean * mean;
    float rstd = rsqrtf(var + LN_EPS);

    const float4* g4 = reinterpret_cast<const float4*>(gamma);
    const float4* b4 = reinterpret_cast<const float4*>(beta);
    float4* o4 = reinterpret_cast<float4*>(xn + (size_t)row * DIM);
    float4 g0 = g4[tid], g1 = g4[tid + 256];
    float4 be0 = b4[tid], be1 = b4[tid + 256];
    float4 o0, o1;
    o0.x = (a.x - mean) * rstd * g0.x + be0.x;
    o0.y = (a.y - mean) * rstd * g0.y + be0.y;
    o0.z = (a.z - mean) * rstd * g0.z + be0.z;
    o0.w = (a.w - mean) * rstd * g0.w + be0.w;
    o1.x = (b.x - mean) * rstd * g1.x + be1.x;
    o1.y = (b.y - mean) * rstd * g1.y + be1.y;
    o1.z = (b.z - mean) * rstd * g1.z + be1.z;
    o1.w = (b.w - mean) * rstd * g1.w + be1.w;
    o4[tid] = o0;
    o4[tid + 256] = o1;
}

// ---------------------------------------------------------------------------
// GEMM tiling: 128x128x8, 256 threads, 8x8 per thread, gmem->reg prefetch.
// ---------------------------------------------------------------------------
#define BM 128
#define BN 128
#define BK 8

// GEMM1: g_h[4096,10368] = g_xn[4096,2048] @ W_in[:, :10368] (ld 18560)
__global__ __launch_bounds__(256) void gemm1_kernel(
        const float* __restrict__ A, const float* __restrict__ Bw,
        float* __restrict__ C) {
    __shared__ float As[BK][BM];
    __shared__ float Bs[BK][BN];
    int tid = threadIdx.x;
    int m0 = blockIdx.y * BM, n0 = blockIdx.x * BN;
    int arow = tid >> 1, acol = (tid & 1) * 4;      // A: 128 rows x 8 cols
    int brow = tid >> 5, bcol = (tid & 31) * 4;     // B: 8 rows x 128 cols
    const float* Ag = A + (size_t)(m0 + arow) * DIM + acol;
    const float* Bg = Bw + (size_t)brow * LDWIN + n0 + bcol;

    float4 aF = *reinterpret_cast<const float4*>(Ag);
    float4 bF = *reinterpret_cast<const float4*>(Bg);
    float acc[8][8];
    #pragma unroll
    for (int i = 0; i < 8; i++)
        #pragma unroll
        for (int j = 0; j < 8; j++) acc[i][j] = 0.0f;

    int tx = tid & 15, ty = tid >> 4;
    const int NT = DIM / BK;
    for (int t = 0; t < NT; t++) {
        As[acol + 0][arow] = aF.x;
        As[acol + 1][arow] = aF.y;
        As[acol + 2][arow] = aF.z;
        As[acol + 3][arow] = aF.w;
        *reinterpret_cast<float4*>(&Bs[brow][bcol]) = bF;
        __syncthreads();
        if (t + 1 < NT) {
            aF = *reinterpret_cast<const float4*>(Ag + (size_t)(t + 1) * BK);
            bF = *reinterpret_cast<const float4*>(Bg + (size_t)(t + 1) * BK * LDWIN);
        }
        #pragma unroll
        for (int kk = 0; kk < BK; kk++) {
            float4 a0 = *reinterpret_cast<float4*>(&As[kk][ty * 8]);
            float4 a1 = *reinterpret_cast<float4*>(&As[kk][ty * 8 + 4]);
            float4 b0 = *reinterpret_cast<float4*>(&Bs[kk][tx * 8]);
            float4 b1 = *reinterpret_cast<float4*>(&Bs[kk][tx * 8 + 4]);
            float ar[8] = {a0.x, a0.y, a0.z, a0.w, a1.x, a1.y, a1.z, a1.w};
            float br[8] = {b0.x, b0.y, b0.z, b0.w, b1.x, b1.y, b1.z, b1.w};
            #pragma unroll
            for (int i = 0; i < 8; i++)
                #pragma unroll
                for (int j = 0; j < 8; j++)
                    acc[i][j] += ar[i] * br[j];
        }
        __syncthreads();
    }
    #pragma unroll
    for (int i = 0; i < 8; i++) {
        float* Cp = C + (size_t)(m0 + ty * 8 + i) * HCOLS + n0 + tx * 8;
        *reinterpret_cast<float4*>(Cp)     = make_float4(acc[i][0], acc[i][1], acc[i][2], acc[i][3]);
        *reinterpret_cast<float4*>(Cp + 4) = make_float4(acc[i][4], acc[i][5], acc[i][6], acc[i][7]);
    }
}

// ---------------------------------------------------------------------------
// Kernel 3: rotary (in-place on q & k regions of g_h) + q scale.
// One block per token row. 1024 q pairs + 32 k pairs.
// ---------------------------------------------------------------------------
__global__ void rotary_kernel(float* __restrict__ h) {
    int row = blockIdx.x;
    int s = row & (SEQ - 1);
    float* hp = h + (size_t)row * HCOLS;
    for (int job = threadIdx.x; job < 1056; job += blockDim.x) {
        int c, base;
        float scl;
        if (job < 1024) { int hd = job >> 5; c = job & 31; base = hd * 64; scl = QSCALE; }
        else            { c = job - 1024; base = NHEAD * DHEAD; scl = 1.0f; }
        // inv_freq = 10000^(-c/32)
        float inv = powf(10000.0f, -(float)c * (1.0f / 32.0f));
        float ang = (float)s * inv;
        float sn, cs;
        sincosf(ang, &sn, &cs);
        float qa = hp[base + c];
        float qb = hp[base + c + 32];
        hp[base + c]      = (qa * cs - qb * sn) * scl;
        hp[base + c + 32] = (qb * cs + qa * sn) * scl;
    }
}

// ---------------------------------------------------------------------------
// Kernel 4: causal MQA flash attention.
// Grid: (SEQ/128, NHEAD, BATCH), 128 threads; one thread = one query row.
// k/v (shared across heads) staged through smem in 64-key tiles.
// ---------------------------------------------------------------------------
__global__ __launch_bounds__(128) void attn_kernel(
        const float* __restrict__ h, float* __restrict__ attn_out) {
    __shared__ float4 ks4[64][16];
    __shared__ float4 vs4[64][16];
    int tid  = threadIdx.x;
    int r    = blockIdx.x * 128 + tid;    // query position in sequence
    int head = blockIdx.y;
    int b    = blockIdx.z;

    const float* qp = h + (size_t)(b * SEQ + r) * HCOLS + head * DHEAD;
    float4 q4[16];
    #pragma unroll
    for (int i = 0; i < 16; i++) q4[i] = reinterpret_cast<const float4*>(qp)[i];

    float4 acc[16];
    #pragma unroll
    for (int i = 0; i < 16; i++) acc[i] = make_float4(0.f, 0.f, 0.f, 0.f);
    float mrow = -INFINITY, lsum = 0.0f;

    int ntile = 2 * (blockIdx.x + 1);     // covers keys 0 .. blockIdx.x*128+127
    for (int t = 0; t < ntile; t++) {
        int j0 = t * 64;
        __syncthreads();
        // cooperative load of k/v tile (64 keys x 64 dims each)
        #pragma unroll
        for (int it = 0; it < 8; it++) {
            int idx = tid + it * 128;
            int jr = idx >> 4, d4 = idx & 15;
            const float* kp = h + (size_t)(b * SEQ + j0 + jr) * HCOLS + NHEAD * DHEAD;
            ks4[jr][d4] = reinterpret_cast<const float4*>(kp)[d4];
            vs4[jr][d4] = reinterpret_cast<const float4*>(kp + DHEAD)[d4];
        }
        __syncthreads();
        int jend = r - j0 + 1;
        if (jend > 64) jend = 64;
        for (int j = 0; j < jend; j++) {
            float dot = 0.0f;
            #pragma unroll
            for (int i = 0; i < 16; i++) {
                float4 kv = ks4[j][i];
                dot += q4[i].x * kv.x + q4[i].y * kv.y + q4[i].z * kv.z + q4[i].w * kv.w;
            }
            if (dot <= mrow) {
                float p = __expf(dot - mrow);
                lsum += p;
                #pragma unroll
                for (int i = 0; i < 16; i++) {
                    float4 vv = vs4[j][i];
                    acc[i].x += p * vv.x; acc[i].y += p * vv.y;
                    acc[i].z += p * vv.z; acc[i].w += p * vv.w;
                }
            } else {
                float sc = __expf(mrow - dot);
                mrow = dot;
                lsum = lsum * sc + 1.0f;
                #pragma unroll
                for (int i = 0; i < 16; i++) {
                    float4 vv = vs4[j][i];
                    acc[i].x = acc[i].x * sc + vv.x; acc[i].y = acc[i].y * sc + vv.y;
                    acc[i].z = acc[i].z * sc + vv.z; acc[i].w = acc[i].w * sc + vv.w;
                }
            }
        }
    }
    float inv = 1.0f / lsum;
    float* op = attn_out + (size_t)(b * SEQ + r) * DIM + head * DHEAD;
    #pragma unroll
    for (int i = 0; i < 16; i++) {
        float4 o = acc[i];
        o.x *= inv; o.y *= inv; o.z *= inv; o.w *= inv;
        reinterpret_cast<float4*>(op)[i] = o;
    }
}

// ---------------------------------------------------------------------------
// GEMM2: out[4096,2048] = concat(attn, ffn) @ W_out + xn
// A columns: f<2048 -> g_attn[row,f]; f>=2048 -> g_h[row, f+128] (ffn slice).
// ---------------------------------------------------------------------------
__global__ __launch_bounds__(256) void gemm2_kernel(
        const float* __restrict__ Aattn, const float* __restrict__ Ah,
        const float* __restrict__ Bw, const float* __restrict__ xn,
        float* __restrict__ out) {
    __shared__ float As[BK][BM];
    __shared__ float Bs[BK][BN];
    int tid = threadIdx.x;
    int m0 = blockIdx.y * BM, n0 = blockIdx.x * BN;
    int arow = tid >> 1, acol = (tid & 1) * 4;
    int brow = tid >> 5, bcol = (tid & 31) * 4;

    const float* attnRow = Aattn + (size_t)(m0 + arow) * DIM;
    const float* hRow    = Ah + (size_t)(m0 + arow) * HCOLS + 128;  // +128: ffn offset shift
    const float* Bg      = Bw + (size_t)brow * DIM + n0 + bcol;

    float4 aF, bF;
    {
        int k0 = 0;
        aF = *reinterpret_cast<const float4*>(attnRow + k0 + acol);
        bF = *reinterpret_cast<const float4*>(Bg);
    }
    float acc[8][8];
    #pragma unroll
    for (int i = 0; i < 8; i++)
        #pragma unroll
        for (int j = 0; j < 8; j++) acc[i][j] = 0.0f;

    int tx = tid & 15, ty = tid >> 4;
    const int NT = OUTK / BK;   // 1280
    for (int t = 0; t < NT; t++) {
        As[acol + 0][arow] = aF.x;
        As[acol + 1][arow] = aF.y;
        As[acol + 2][arow] = aF.z;
        As[acol + 3][arow] = aF.w;
        *reinterpret_cast<float4*>(&Bs[brow][bcol]) = bF;
        __syncthreads();
        if (t + 1 < NT) {
            int k0 = (t + 1) * BK;
            if (k0 < DIM)
                aF = *reinterpret_cast<const float4*>(attnRow + k0 + acol);
            else
                aF = *reinterpret_cast<const float4*>(hRow + k0 + acol);
            bF = *reinterpret_cast<const float4*>(Bg + (size_t)k0 * DIM);
        }
        #pragma unroll
        for (int kk = 0; kk < BK; kk++) {
            float4 a0 = *reinterpret_cast<float4*>(&As[kk][ty * 8]);
            float4 a1 = *reinterpret_cast<float4*>(&As[kk][ty * 8 + 4]);
            float4 b0 = *reinterpret_cast<float4*>(&Bs[kk][tx * 8]);
            float4 b1 = *reinterpret_cast<float4*>(&Bs[kk][tx * 8 + 4]);
            float ar[8] = {a0.x, a0.y, a0.z, a0.w, a1.x, a1.y, a1.z, a1.w};
            float br[8] = {b0.x, b0.y, b0.z, b0.w, b1.x, b1.y, b1.z, b1.w};
            #pragma unroll
            for (int i = 0; i < 8; i++)
                #pragma unroll
                for (int j = 0; j < 8; j++)
                    acc[i][j] += ar[i] * br[j];
        }
        __syncthreads();
    }
    #pragma unroll
    for (int i = 0; i < 8; i++) {
        size_t base = (size_t)(m0 + ty * 8 + i) * DIM + n0 + tx * 8;
        float4 r0 = *reinterpret_cast<const float4*>(xn + base);
        float4 r1 = *reinterpret_cast<const float4*>(xn + base + 4);
        *reinterpret_cast<float4*>(out + base) =
            make_float4(acc[i][0] + r0.x, acc[i][1] + r0.y, acc[i][2] + r0.z, acc[i][3] + r0.w);
        *reinterpret_cast<float4*>(out + base + 4) =
            make_float4(acc[i][4] + r1.x, acc[i][5] + r1.y, acc[i][6] + r1.z, acc[i][7] + r1.w);
    }
}

// ---------------------------------------------------------------------------
extern "C" void kernel_launch(void* const* d_in, const int* in_sizes, int n_in,
                              void* d_out, int out_size) {
    const float* x     = (const float*)d_in[0];   // [2,2048,2048]
    const float* W_in  = (const float*)d_in[1];   // [2048,18560]
    const float* W_out = (const float*)d_in[2];   // [10240,2048]
    const float* gamma = (const float*)d_in[3];   // [2048]
    const float* beta  = (const float*)d_in[4];   // [2048]
    float* out = (float*)d_out;                   // [2,2048,2048]

    float* xn;   cudaGetSymbolAddress((void**)&xn,   g_xn);
    float* h;    cudaGetSymbolAddress((void**)&h,    g_h);
    float* attn; cudaGetSymbolAddress((void**)&attn, g_attn);

    ln_kernel<<<MTOK, 256>>>(x, gamma, beta, xn);
    gemm1_kernel<<<dim3(HCOLS / BN, MTOK / BM), 256>>>(xn, W_in, h);
    rotary_kernel<<<MTOK, 128>>>(h);
    attn_kernel<<<dim3(SEQ / 128, NHEAD, BATCH), 128>>>(h, attn);
    gemm2_kernel<<<dim3(DIM / BN, MTOK / BM), 256>>>(attn, h, W_out, xn, out);
}

// round 3
// speedup vs baseline: 2.1272x; 2.1272x over previous
#include <cuda_runtime.h>
#include <cuda_bf16.h>
#include <math.h>
#include <stdint.h>

// ---------------------------------------------------------------------------
// Problem constants
// ---------------------------------------------------------------------------
#define BATCH 2
#define SEQ   2048
#define DIM   2048
#define NHEAD 32
#define DHEAD 64
#define FFN   8192
#define LDWIN 18560              // W_in row stride (full)
#define HCOLS 10368              // used cols of W_in: q|k|v|ffn
#define OUTK  10240              // concat dim: attn(2048)+ffn(8192)
#define MTOK  (BATCH*SEQ)
#define LN_EPS 1e-5f
#define QSCALE 0.125f

// ---------------------------------------------------------------------------
// Scratch (device globals)
// ---------------------------------------------------------------------------
__device__ float g_xn[(size_t)MTOK * DIM];      // LN output (residual)
__device__ float g_h[(size_t)MTOK * HCOLS];     // GEMM1 output fp32
__device__ __nv_bfloat16 g_a1hi[(size_t)MTOK * DIM];
__device__ __nv_bfloat16 g_a1lo[(size_t)MTOK * DIM];
__device__ __nv_bfloat16 g_w1hi[(size_t)HCOLS * DIM];   // W_in^T split [10368,2048]
__device__ __nv_bfloat16 g_w1lo[(size_t)HCOLS * DIM];
__device__ __nv_bfloat16 g_a2hi[(size_t)MTOK * OUTK];   // concat split [4096,10240]
__device__ __nv_bfloat16 g_a2lo[(size_t)MTOK * OUTK];
__device__ __nv_bfloat16 g_w2hi[(size_t)DIM * OUTK];    // W_out^T split [2048,10240]
__device__ __nv_bfloat16 g_w2lo[(size_t)DIM * OUTK];

// ---------------------------------------------------------------------------
// PTX helpers (sm_80-era: cp.async + ldmatrix + mma.sync — legal on compute_103)
// ---------------------------------------------------------------------------
__device__ __forceinline__ uint32_t smem_u32(const void* p) {
    uint32_t a;
    asm("{ .reg .u64 t; cvta.to.shared.u64 t, %1; cvt.u32.u64 %0, t; }" : "=r"(a) : "l"(p));
    return a;
}
#define CP_ASYNC16(sa, gp) \
    asm volatile("cp.async.cg.shared.global [%0], [%1], 16;" :: "r"(sa), "l"(gp))
#define CP_COMMIT() asm volatile("cp.async.commit_group;" ::: "memory")
#define CP_WAIT(n)  asm volatile("cp.async.wait_group %0;" :: "n"(n) : "memory")

#define LDSM_X4(r0, r1, r2, r3, addr) \
    asm volatile("ldmatrix.sync.aligned.m8n8.x4.shared.b16 {%0,%1,%2,%3}, [%4];" \
        : "=r"(r0), "=r"(r1), "=r"(r2), "=r"(r3) : "r"(addr))

#define MMA16816(d, a0, a1, a2, a3, b0, b1) \
    asm volatile("mma.sync.aligned.m16n8k16.row.col.f32.bf16.bf16.f32 " \
        "{%0,%1,%2,%3}, {%4,%5,%6,%7}, {%8,%9}, {%0,%1,%2,%3};" \
        : "+f"((d)[0]), "+f"((d)[1]), "+f"((d)[2]), "+f"((d)[3]) \
        : "r"(a0), "r"(a1), "r"(a2), "r"(a3), "r"(b0), "r"(b1))

__device__ __forceinline__ __nv_bfloat162 bf2hi(float x, float y) {
    return __halves2bfloat162(__float2bfloat16(x), __float2bfloat16(y));
}
__device__ __forceinline__ __nv_bfloat162 bf2lo(float x, float y) {
    float rx = x - __bfloat162float(__float2bfloat16(x));
    float ry = y - __bfloat162float(__float2bfloat16(y));
    return __halves2bfloat162(__float2bfloat16(rx), __float2bfloat16(ry));
}

// ---------------------------------------------------------------------------
// Kernel 1: LayerNorm + bf16 split of output (A1 for GEMM1)
// ---------------------------------------------------------------------------
__global__ void ln_split_kernel(const float* __restrict__ x,
                                const float* __restrict__ gamma,
                                const float* __restrict__ beta,
                                float* __restrict__ xn,
                                __nv_bfloat16* __restrict__ ahi,
                                __nv_bfloat16* __restrict__ alo) {
    int row = blockIdx.x;
    int tid = threadIdx.x;
    const float4* xr = reinterpret_cast<const float4*>(x + (size_t)row * DIM);
    float4 a = xr[tid];
    float4 b = xr[tid + 256];
    float s  = a.x + a.y + a.z + a.w + b.x + b.y + b.z + b.w;
    float s2 = a.x*a.x + a.y*a.y + a.z*a.z + a.w*a.w
             + b.x*b.x + b.y*b.y + b.z*b.z + b.w*b.w;
    #pragma unroll
    for (int off = 16; off > 0; off >>= 1) {
        s  += __shfl_xor_sync(0xffffffffu, s,  off);
        s2 += __shfl_xor_sync(0xffffffffu, s2, off);
    }
    __shared__ float ss[8], ss2[8];
    int wid = tid >> 5, lane = tid & 31;
    if (lane == 0) { ss[wid] = s; ss2[wid] = s2; }
    __syncthreads();
    s  = ss[0] + ss[1] + ss[2] + ss[3] + ss[4] + ss[5] + ss[6] + ss[7];
    s2 = ss2[0]+ ss2[1]+ ss2[2]+ ss2[3]+ ss2[4]+ ss2[5]+ ss2[6]+ ss2[7];
    float mean = s * (1.0f / DIM);
    float var  = s2 * (1.0f / DIM) - mean * mean;
    float rstd = rsqrtf(var + LN_EPS);

    const float4* g4 = reinterpret_cast<const float4*>(gamma);
    const float4* b4 = reinterpret_cast<const float4*>(beta);
    float4 g0 = g4[tid], g1 = g4[tid + 256];
    float4 be0 = b4[tid], be1 = b4[tid + 256];
    float4 o0, o1;
    o0.x = (a.x - mean) * rstd * g0.x + be0.x;
    o0.y = (a.y - mean) * rstd * g0.y + be0.y;
    o0.z = (a.z - mean) * rstd * g0.z + be0.z;
    o0.w = (a.w - mean) * rstd * g0.w + be0.w;
    o1.x = (b.x - mean) * rstd * g1.x + be1.x;
    o1.y = (b.y - mean) * rstd * g1.y + be1.y;
    o1.z = (b.z - mean) * rstd * g1.z + be1.z;
    o1.w = (b.w - mean) * rstd * g1.w + be1.w;
    float4* o4 = reinterpret_cast<float4*>(xn + (size_t)row * DIM);
    o4[tid] = o0;
    o4[tid + 256] = o1;

    __nv_bfloat162* ph = reinterpret_cast<__nv_bfloat162*>(ahi + (size_t)row * DIM);
    __nv_bfloat162* pl = reinterpret_cast<__nv_bfloat162*>(alo + (size_t)row * DIM);
    ph[tid*2+0]   = bf2hi(o0.x, o0.y);  pl[tid*2+0]   = bf2lo(o0.x, o0.y);
    ph[tid*2+1]   = bf2hi(o0.z, o0.w);  pl[tid*2+1]   = bf2lo(o0.z, o0.w);
    ph[tid*2+512] = bf2hi(o1.x, o1.y);  pl[tid*2+512] = bf2lo(o1.x, o1.y);
    ph[tid*2+513] = bf2hi(o1.z, o1.w);  pl[tid*2+513] = bf2lo(o1.z, o1.w);
}

// ---------------------------------------------------------------------------
// Kernel 2: transpose + bf16 split of weight matrices.
// ---------------------------------------------------------------------------
__global__ void tsplit_kernel(const float* __restrict__ src, int ld_src,
                              __nv_bfloat16* __restrict__ dhi,
                              __nv_bfloat16* __restrict__ dlo, int ld_dst) {
    __shared__ float t[32][33];
    int n0 = blockIdx.x * 32, k0 = blockIdx.y * 32;
    int tx = threadIdx.x, ty = threadIdx.y;
    #pragma unroll
    for (int i = 0; i < 4; i++)
        t[ty + 8*i][tx] = src[(size_t)(k0 + ty + 8*i) * ld_src + n0 + tx];
    __syncthreads();
    #pragma unroll
    for (int i = 0; i < 4; i++) {
        float v = t[tx][ty + 8*i];
        size_t o = (size_t)(n0 + ty + 8*i) * ld_dst + k0 + tx;
        __nv_bfloat16 h = __float2bfloat16(v);
        dhi[o] = h;
        dlo[o] = __float2bfloat16(v - __bfloat162float(h));
    }
}

// ---------------------------------------------------------------------------
// Tensor-core GEMM (mma.sync bf16, 3-term hi/lo split).
// C[M,N] = (Ahi+Alo)[M,K] @ (Bhi+Blo)^T ([N,K] K-major), fp32 accum.
// CTA tile 128x128, K-chunk 32, 3-stage cp.async pipeline, 256 threads.
// SMEM row stride 40 bf16 (80 B) -> conflict-free ldmatrix.
// ---------------------------------------------------------------------------
#define BK     32
#define SROWB  80            // bytes per smem row (32 bf16 + 4 pad)
#define OFF_ALO 10240
#define OFF_BHI 20480
#define OFF_BLO 30720
#define STAGEB  40960
#define NSTAGE  3

template <bool RES>
__global__ __launch_bounds__(256, 1) void gemm_mma(
        const __nv_bfloat16* __restrict__ Ahi, const __nv_bfloat16* __restrict__ Alo,
        const __nv_bfloat16* __restrict__ Bhi, const __nv_bfloat16* __restrict__ Blo,
        float* __restrict__ C, int K, int ldc, const float* __restrict__ resid) {
    extern __shared__ __align__(16) char dsm[];
    uint32_t sbase = smem_u32(dsm);

    int tid  = threadIdx.x;
    int wid  = tid >> 5;
    int lane = tid & 31;
    int wm   = wid & 3;          // M quarter (32 rows)
    int wn   = wid >> 2;         // N half   (64 cols)

    int m0 = blockIdx.x * 128;   // grid.x = M tiles -> wave shares B tiles
    int n0 = blockIdx.y * 128;

    // cp.async per-thread mapping: 512 16B-chunks per (sub)tile, 2 per thread
    uint32_t sO[2]; size_t gO[2];
    #pragma unroll
    for (int i = 0; i < 2; i++) {
        int idx = tid + i * 256;
        int row = idx >> 2, c = idx & 3;
        sO[i] = (uint32_t)(row * SROWB + c * 16);
        gO[i] = (size_t)row * K + c * 8;
    }
    const __nv_bfloat16* gAhi = Ahi + (size_t)m0 * K;
    const __nv_bfloat16* gAlo = Alo + (size_t)m0 * K;
    const __nv_bfloat16* gBhi = Bhi + (size_t)n0 * K;
    const __nv_bfloat16* gBlo = Blo + (size_t)n0 * K;

    const int NC = K / BK;

    auto load_chunk = [&](int c) {
        uint32_t base = sbase + (uint32_t)(c % NSTAGE) * STAGEB;
        size_t co = (size_t)c * BK;
        #pragma unroll
        for (int i = 0; i < 2; i++) {
            CP_ASYNC16(base + sO[i],           (const void*)(gAhi + gO[i] + co));
            CP_ASYNC16(base + OFF_ALO + sO[i], (const void*)(gAlo + gO[i] + co));
            CP_ASYNC16(base + OFF_BHI + sO[i], (const void*)(gBhi + gO[i] + co));
            CP_ASYNC16(base + OFF_BLO + sO[i], (const void*)(gBlo + gO[i] + co));
        }
    };

    float acc[2][8][4];
    #pragma unroll
    for (int i = 0; i < 2; i++)
        #pragma unroll
        for (int j = 0; j < 8; j++)
            #pragma unroll
            for (int v = 0; v < 4; v++) acc[i][j][v] = 0.0f;

    // prologue: fill pipeline
    #pragma unroll
    for (int c = 0; c < NSTAGE - 1; c++) { load_chunk(c); CP_COMMIT(); }

    // ldmatrix per-thread address components (byte offsets within a subtile)
    uint32_t aBase = (uint32_t)((wm * 32 + (lane & 15)) * SROWB + (lane >> 4) * 16);
    uint32_t bBase = (uint32_t)((wn * 64 + (lane & 15)) * SROWB + (lane >> 4) * 16);

    const uint32_t passA[3] = {0u, 0u, (uint32_t)OFF_ALO};
    const uint32_t passB[3] = {(uint32_t)OFF_BHI, (uint32_t)OFF_BLO, (uint32_t)OFF_BHI};

    for (int c = 0; c < NC; c++) {
        CP_WAIT(NSTAGE - 2);
        __syncthreads();
        // issue loads for chunk c + NSTAGE - 1 (overwrites buffer of chunk c-1)
        if (c + NSTAGE - 1 < NC) load_chunk(c + NSTAGE - 1);
        CP_COMMIT();

        uint32_t buf = sbase + (uint32_t)(c % NSTAGE) * STAGEB;
        #pragma unroll
        for (int p = 0; p < 3; p++) {
            uint32_t ab = buf + passA[p] + aBase;
            uint32_t bb = buf + passB[p] + bBase;
            #pragma unroll
            for (int ks = 0; ks < 2; ks++) {
                uint32_t a0[4], a1[4], b0[4], b1[4];
                LDSM_X4(a0[0], a0[1], a0[2], a0[3], ab + ks * 32);
                LDSM_X4(a1[0], a1[1], a1[2], a1[3], ab + 16 * SROWB + ks * 32);
                LDSM_X4(b0[0], b0[1], b0[2], b0[3], bb + ks * 32);
                LDSM_X4(b1[0], b1[1], b1[2], b1[3], bb + 16 * SROWB + ks * 32);
                // b-regs: {n0-7 k0-7, n8-15 k0-7, n0-7 k8-15, n8-15 k8-15}
                MMA16816(acc[0][0], a0[0], a0[1], a0[2], a0[3], b0[0], b0[2]);
                MMA16816(acc[0][1], a0[0], a0[1], a0[2], a0[3], b0[1], b0[3]);
                MMA16816(acc[0][2], a0[0], a0[1], a0[2], a0[3], b1[0], b1[2]);
                MMA16816(acc[0][3], a0[0], a0[1], a0[2], a0[3], b1[1], b1[3]);
                MMA16816(acc[1][0], a1[0], a1[1], a1[2], a1[3], b0[0], b0[2]);
                MMA16816(acc[1][1], a1[0], a1[1], a1[2], a1[3], b0[1], b0[3]);
                MMA16816(acc[1][2], a1[0], a1[1], a1[2], a1[3], b1[0], b1[2]);
                MMA16816(acc[1][3], a1[0], a1[1], a1[2], a1[3], b1[1], b1[3]);
                uint32_t bb2 = bb + 32 * SROWB;
                LDSM_X4(b0[0], b0[1], b0[2], b0[3], bb2 + ks * 32);
                LDSM_X4(b1[0], b1[1], b1[2], b1[3], bb2 + 16 * SROWB + ks * 32);
                MMA16816(acc[0][4], a0[0], a0[1], a0[2], a0[3], b0[0], b0[2]);
                MMA16816(acc[0][5], a0[0], a0[1], a0[2], a0[3], b0[1], b0[3]);
                MMA16816(acc[0][6], a0[0], a0[1], a0[2], a0[3], b1[0], b1[2]);
                MMA16816(acc[0][7], a0[0], a0[1], a0[2], a0[3], b1[1], b1[3]);
                MMA16816(acc[1][4], a1[0], a1[1], a1[2], a1[3], b0[0], b0[2]);
                MMA16816(acc[1][5], a1[0], a1[1], a1[2], a1[3], b0[1], b0[3]);
                MMA16816(acc[1][6], a1[0], a1[1], a1[2], a1[3], b1[0], b1[2]);
                MMA16816(acc[1][7], a1[0], a1[1], a1[2], a1[3], b1[1], b1[3]);
            }
        }
        __syncthreads();
    }

    // Epilogue: acc[mt][nt][{c0,c1,c2,c3}]
    int g = lane >> 2, q = lane & 3;
    #pragma unroll
    for (int mt = 0; mt < 2; mt++) {
        #pragma unroll
        for (int nt = 0; nt < 8; nt++) {
            int rowm = m0 + wm * 32 + mt * 16 + g;
            int coln = n0 + wn * 64 + nt * 8 + q * 2;
            float* p0 = C + (size_t)rowm * ldc + coln;
            float* p1 = C + (size_t)(rowm + 8) * ldc + coln;
            float2 v0 = make_float2(acc[mt][nt][0], acc[mt][nt][1]);
            float2 v1 = make_float2(acc[mt][nt][2], acc[mt][nt][3]);
            if (RES) {
                const float2 r0 = *reinterpret_cast<const float2*>(resid + (size_t)rowm * ldc + coln);
                const float2 r1 = *reinterpret_cast<const float2*>(resid + (size_t)(rowm + 8) * ldc + coln);
                v0.x += r0.x; v0.y += r0.y;
                v1.x += r1.x; v1.y += r1.y;
            }
            *reinterpret_cast<float2*>(p0) = v0;
            *reinterpret_cast<float2*>(p1) = v1;
        }
    }
}

// ---------------------------------------------------------------------------
// Kernel: rotary (in-place on q & k regions of g_h) + q scale.
// ---------------------------------------------------------------------------
__global__ void rotary_kernel(float* __restrict__ h) {
    int row = blockIdx.x;
    int s = row & (SEQ - 1);
    float* hp = h + (size_t)row * HCOLS;
    for (int job = threadIdx.x; job < 1056; job += blockDim.x) {
        int c, base;
        float scl;
        if (job < 1024) { int hd = job >> 5; c = job & 31; base = hd * 64; scl = QSCALE; }
        else            { c = job - 1024; base = NHEAD * DHEAD; scl = 1.0f; }
        float inv = powf(10000.0f, -(float)c * (1.0f / 32.0f));
        float ang = (float)s * inv;
        float sn, cs;
        sincosf(ang, &sn, &cs);
        float qa = hp[base + c];
        float qb = hp[base + c + 32];
        hp[base + c]      = (qa * cs - qb * sn) * scl;
        hp[base + c + 32] = (qb * cs + qa * sn) * scl;
    }
}

// ---------------------------------------------------------------------------
// Kernel: causal MQA flash attention -> writes bf16 hi/lo into A2 cols [0,2048)
// ---------------------------------------------------------------------------
__global__ __launch_bounds__(128) void attn_kernel(
        const float* __restrict__ h,
        __nv_bfloat16* __restrict__ a2hi, __nv_bfloat16* __restrict__ a2lo) {
    __shared__ float4 ks4[64][16];
    __shared__ float4 vs4[64][16];
    int tid  = threadIdx.x;
    int r    = blockIdx.x * 128 + tid;
    int head = blockIdx.y;
    int b    = blockIdx.z;

    const float* qp = h + (size_t)(b * SEQ + r) * HCOLS + head * DHEAD;
    float4 q4[16];
    #pragma unroll
    for (int i = 0; i < 16; i++) q4[i] = reinterpret_cast<const float4*>(qp)[i];

    float4 acc[16];
    #pragma unroll
    for (int i = 0; i < 16; i++) acc[i] = make_float4(0.f, 0.f, 0.f, 0.f);
    float mrow = -INFINITY, lsum = 0.0f;

    int ntile = 2 * (blockIdx.x + 1);
    for (int t = 0; t < ntile; t++) {
        int j0 = t * 64;
        __syncthreads();
        #pragma unroll
        for (int it = 0; it < 8; it++) {
            int idx = tid + it * 128;
            int jr = idx >> 4, d4 = idx & 15;
            const float* kp = h + (size_t)(b * SEQ + j0 + jr) * HCOLS + NHEAD * DHEAD;
            ks4[jr][d4] = reinterpret_cast<const float4*>(kp)[d4];
            vs4[jr][d4] = reinterpret_cast<const float4*>(kp + DHEAD)[d4];
        }
        __syncthreads();
        int jend = r - j0 + 1;
        if (jend > 64) jend = 64;
        for (int j = 0; j < jend; j++) {
            float dot = 0.0f;
            #pragma unroll
            for (int i = 0; i < 16; i++) {
                float4 kv = ks4[j][i];
                dot += q4[i].x * kv.x + q4[i].y * kv.y + q4[i].z * kv.z + q4[i].w * kv.w;
            }
            if (dot <= mrow) {
                float p = __expf(dot - mrow);
                lsum += p;
                #pragma unroll
                for (int i = 0; i < 16; i++) {
                    float4 vv = vs4[j][i];
                    acc[i].x += p * vv.x; acc[i].y += p * vv.y;
                    acc[i].z += p * vv.z; acc[i].w += p * vv.w;
                }
            } else {
                float sc = __expf(mrow - dot);
                mrow = dot;
                lsum = lsum * sc + 1.0f;
                #pragma unroll
                for (int i = 0; i < 16; i++) {
                    float4 vv = vs4[j][i];
                    acc[i].x = acc[i].x * sc + vv.x; acc[i].y = acc[i].y * sc + vv.y;
                    acc[i].z = acc[i].z * sc + vv.z; acc[i].w = acc[i].w * sc + vv.w;
                }
            }
        }
    }
    float inv = 1.0f / lsum;
    size_t ob = (size_t)(b * SEQ + r) * OUTK + head * DHEAD;
    __nv_bfloat162* ph = reinterpret_cast<__nv_bfloat162*>(a2hi + ob);
    __nv_bfloat162* pl = reinterpret_cast<__nv_bfloat162*>(a2lo + ob);
    #pragma unroll
    for (int i = 0; i < 16; i++) {
        float4 o = acc[i];
        o.x *= inv; o.y *= inv; o.z *= inv; o.w *= inv;
        ph[i*2+0] = bf2hi(o.x, o.y);  pl[i*2+0] = bf2lo(o.x, o.y);
        ph[i*2+1] = bf2hi(o.z, o.w);  pl[i*2+1] = bf2lo(o.z, o.w);
    }
}

// ---------------------------------------------------------------------------
// Kernel: split ffn region of g_h into A2 cols [2048, 10240)
// ---------------------------------------------------------------------------
__global__ void ffn_split_kernel(const float* __restrict__ h,
                                 __nv_bfloat16* __restrict__ a2hi,
                                 __nv_bfloat16* __restrict__ a2lo) {
    size_t i = (size_t)blockIdx.x * blockDim.x + threadIdx.x; // over 4096*2048 float4
    int m  = (int)(i >> 11);
    int j4 = (int)(i & 2047);
    float4 v = *reinterpret_cast<const float4*>(h + (size_t)m * HCOLS + 2176 + j4 * 4);
    size_t ob = (size_t)m * OUTK + 2048 + j4 * 4;
    __nv_bfloat162* ph = reinterpret_cast<__nv_bfloat162*>(a2hi + ob);
    __nv_bfloat162* pl = reinterpret_cast<__nv_bfloat162*>(a2lo + ob);
    ph[0] = bf2hi(v.x, v.y);  pl[0] = bf2lo(v.x, v.y);
    ph[1] = bf2hi(v.z, v.w);  pl[1] = bf2lo(v.z, v.w);
}

// ---------------------------------------------------------------------------
extern "C" void kernel_launch(void* const* d_in, const int* in_sizes, int n_in,
                              void* d_out, int out_size) {
    const float* x     = (const float*)d_in[0];
    const float* W_in  = (const float*)d_in[1];
    const float* W_out = (const float*)d_in[2];
    const float* gamma = (const float*)d_in[3];
    const float* beta  = (const float*)d_in[4];
    float* out = (float*)d_out;

    float* xn;  cudaGetSymbolAddress((void**)&xn,  g_xn);
    float* h;   cudaGetSymbolAddress((void**)&h,   g_h);
    __nv_bfloat16 *a1hi, *a1lo, *w1hi, *w1lo, *a2hi, *a2lo, *w2hi, *w2lo;
    cudaGetSymbolAddress((void**)&a1hi, g_a1hi);
    cudaGetSymbolAddress((void**)&a1lo, g_a1lo);
    cudaGetSymbolAddress((void**)&w1hi, g_w1hi);
    cudaGetSymbolAddress((void**)&w1lo, g_w1lo);
    cudaGetSymbolAddress((void**)&a2hi, g_a2hi);
    cudaGetSymbolAddress((void**)&a2lo, g_a2lo);
    cudaGetSymbolAddress((void**)&w2hi, g_w2hi);
    cudaGetSymbolAddress((void**)&w2lo, g_w2lo);

    const int SMEM = NSTAGE * STAGEB;   // 122880
    cudaFuncSetAttribute(gemm_mma<false>, cudaFuncAttributeMaxDynamicSharedMemorySize, SMEM);
    cudaFuncSetAttribute(gemm_mma<true>,  cudaFuncAttributeMaxDynamicSharedMemorySize, SMEM);

    ln_split_kernel<<<MTOK, 256>>>(x, gamma, beta, xn, a1hi, a1lo);
    tsplit_kernel<<<dim3(HCOLS/32, DIM/32), dim3(32, 8)>>>(W_in, LDWIN, w1hi, w1lo, DIM);
    tsplit_kernel<<<dim3(DIM/32, OUTK/32), dim3(32, 8)>>>(W_out, DIM, w2hi, w2lo, OUTK);
    gemm_mma<false><<<dim3(MTOK/128, HCOLS/128), 256, SMEM>>>(
        a1hi, a1lo, w1hi, w1lo, h, DIM, HCOLS, nullptr);
    rotary_kernel<<<MTOK, 128>>>(h);
    attn_kernel<<<dim3(SEQ/128, NHEAD, BATCH), 128>>>(h, a2hi, a2lo);
    ffn_split_kernel<<<(MTOK * 2048) / 256, 256>>>(h, a2hi, a2lo);
    gemm_mma<true><<<dim3(MTOK/128, DIM/128), 256, SMEM>>>(
        a2hi, a2lo, w2hi, w2lo, out, OUTK, DIM, xn);
}